// round 1
// baseline (speedup 1.0000x reference)
#include <cuda_runtime.h>
#include <math.h>

// Problem constants
#define BB 4
#define SS 2048
#define DD 1024
#define HH 16
#define DHH 64
#define FFD 4096
#define NROWS (BB*SS)          // 8192

// ---------------- scratch (device globals: allocation-guard safe) ----------
__device__ float g_h   [(size_t)NROWS * DD];        // LN1 out
__device__ float g_h2  [(size_t)NROWS * DD];        // LN2 out
__device__ float g_wqkv[(size_t)DD * 3 * DD];       // packed [1024, 3072]
__device__ float g_qkv [(size_t)NROWS * 3 * DD];    // [8192, 3072]
__device__ float g_attn[(size_t)NROWS * DD];        // concat attention out
__device__ float g_ff1 [(size_t)NROWS * FFD];       // FFN hidden

// ---------------- LayerNorm: one block (256 thr) per row of 1024 ----------
__global__ __launch_bounds__(256) void ln_kernel(const float* __restrict__ x,
                                                 const float* __restrict__ gamma,
                                                 const float* __restrict__ beta,
                                                 float* __restrict__ out) {
    __shared__ float red[8];
    __shared__ float s_mean, s_rstd;
    int row = blockIdx.x, tid = threadIdx.x;
    const float* xr = x + (size_t)row * DD;
    float4 v = *(const float4*)(xr + tid * 4);
    float s = v.x + v.y + v.z + v.w;
#pragma unroll
    for (int off = 16; off; off >>= 1) s += __shfl_xor_sync(0xffffffffu, s, off);
    if ((tid & 31) == 0) red[tid >> 5] = s;
    __syncthreads();
    if (tid == 0) {
        float t = 0.f;
#pragma unroll
        for (int i = 0; i < 8; ++i) t += red[i];
        s_mean = t * (1.0f / DD);
    }
    __syncthreads();
    float mean = s_mean;
    float dx = v.x - mean, dy = v.y - mean, dz = v.z - mean, dw = v.w - mean;
    float sq = dx*dx + dy*dy + dz*dz + dw*dw;
#pragma unroll
    for (int off = 16; off; off >>= 1) sq += __shfl_xor_sync(0xffffffffu, sq, off);
    if ((tid & 31) == 0) red[tid >> 5] = sq;
    __syncthreads();
    if (tid == 0) {
        float t = 0.f;
#pragma unroll
        for (int i = 0; i < 8; ++i) t += red[i];
        s_rstd = rsqrtf(t * (1.0f / DD) + 1e-5f);
    }
    __syncthreads();
    float rstd = s_rstd;
    float4 g4 = *(const float4*)(gamma + tid * 4);
    float4 b4 = *(const float4*)(beta + tid * 4);
    float4 o;
    o.x = dx * rstd * g4.x + b4.x;
    o.y = dy * rstd * g4.y + b4.y;
    o.z = dz * rstd * g4.z + b4.z;
    o.w = dw * rstd * g4.w + b4.w;
    *(float4*)(out + (size_t)row * DD + tid * 4) = o;
}

// ---------------- pack wq/wk/wv [H,D,DH] -> B matrix [D, 3D] --------------
__global__ __launch_bounds__(256) void repack_wqkv(const float* __restrict__ wq,
                                                   const float* __restrict__ wk,
                                                   const float* __restrict__ wv,
                                                   float* __restrict__ wqkv) {
    int idx = blockIdx.x * 256 + threadIdx.x;      // over 1024*3072
    int d = idx / (3 * DD);
    int n = idx - d * (3 * DD);
    int part = n >> 10;          // 0:q 1:k 2:v
    int c = n & 1023;
    int h = c >> 6, e = c & 63;
    const float* w = (part == 0) ? wq : (part == 1) ? wk : wv;
    wqkv[idx] = w[((size_t)h * DD + d) * DHH + e];
}

// ---------------- SGEMM: C[M,N] = A[M,K] @ B[K,N] (+epilogue) -------------
// EPI 0: none      1: +res        2: +bias, gelu(exact)      3: +bias +res
__device__ __forceinline__ float gelu_exact(float v) {
    return 0.5f * v * (1.0f + erff(v * 0.70710678118654752f));
}

template<int EPI>
__global__ __launch_bounds__(256) void sgemm_kernel(
    const float* __restrict__ A, const float* __restrict__ B, float* __restrict__ C,
    const float* __restrict__ bias, const float* __restrict__ res,
    int M, int N, int K) {
    __shared__ float As[16][128];
    __shared__ float Bs[16][128];
    int tid = threadIdx.x;
    int ty = tid >> 4, tx = tid & 15;
    int m0 = blockIdx.y << 7, n0 = blockIdx.x << 7;
    float acc[8][8] = {};
    const float* Ab = A + (size_t)m0 * K;
    const float* Bb = B + n0;
    for (int k0 = 0; k0 < K; k0 += 16) {
#pragma unroll
        for (int q = 0; q < 2; ++q) {
            int f = q * 256 + tid;                 // 0..511 float4s
            int r = f >> 2, kb = (f & 3) << 2;
            float4 v = *(const float4*)(Ab + (size_t)r * K + k0 + kb);
            As[kb + 0][r] = v.x; As[kb + 1][r] = v.y;
            As[kb + 2][r] = v.z; As[kb + 3][r] = v.w;
        }
#pragma unroll
        for (int q = 0; q < 2; ++q) {
            int f = q * 256 + tid;
            int k = f >> 5, nb = (f & 31) << 2;
            *(float4*)(&Bs[k][nb]) = *(const float4*)(Bb + (size_t)(k0 + k) * N + nb);
        }
        __syncthreads();
#pragma unroll
        for (int k = 0; k < 16; ++k) {
            float4 a0 = *(const float4*)(&As[k][ty * 8]);
            float4 a1 = *(const float4*)(&As[k][ty * 8 + 4]);
            float4 b0 = *(const float4*)(&Bs[k][tx * 8]);
            float4 b1 = *(const float4*)(&Bs[k][tx * 8 + 4]);
            float a[8] = {a0.x, a0.y, a0.z, a0.w, a1.x, a1.y, a1.z, a1.w};
            float bb[8] = {b0.x, b0.y, b0.z, b0.w, b1.x, b1.y, b1.z, b1.w};
#pragma unroll
            for (int i = 0; i < 8; ++i)
#pragma unroll
                for (int j = 0; j < 8; ++j)
                    acc[i][j] = fmaf(a[i], bb[j], acc[i][j]);
        }
        __syncthreads();
    }
#pragma unroll
    for (int i = 0; i < 8; ++i) {
        int r = m0 + ty * 8 + i;
#pragma unroll
        for (int j = 0; j < 8; ++j) {
            int c = n0 + tx * 8 + j;
            float v = acc[i][j];
            if (EPI == 1) v += res[(size_t)r * N + c];
            if (EPI == 2) { v += bias[c]; v = gelu_exact(v); }
            if (EPI == 3) v += bias[c] + res[(size_t)r * N + c];
            C[(size_t)r * N + c] = v;
        }
    }
}

// ---------------- Flash attention (causal), fp32, DH=64 -------------------
// qkv: [8192, 3072]  (cols: q at h*64+e, k at 1024+..., v at 2048+...)
// 64 queries x 64 keys per tile. 256 threads = 16x16, each 4x4.
#define FA_PAD 68
#define FA_SMEM (3 * 64 * FA_PAD * 4)

__global__ __launch_bounds__(256) void flash_attn_kernel(const float* __restrict__ qkv,
                                                         float* __restrict__ attn) {
    extern __shared__ float sm[];
    float* Qs = sm;                       // 64 x FA_PAD
    float* Ks = sm + 64 * FA_PAD;         // reused for P after scores
    float* Vs = sm + 2 * 64 * FA_PAD;
    int tid = threadIdx.x;
    int ty = tid >> 4, tx = tid & 15;
    int qt = blockIdx.x;
    int b = blockIdx.y >> 4, h = blockIdx.y & 15;
    int q0 = qt * 64;
    const float* qbase = qkv + ((size_t)(b * SS + q0)) * (3 * DD) + h * DHH;
    const float* kbase = qkv + ((size_t)(b * SS)) * (3 * DD) + DD + h * DHH;
    const float* vbase = qkv + ((size_t)(b * SS)) * (3 * DD) + 2 * DD + h * DHH;

    // load Q, pre-scaled by 1/sqrt(DH)=0.125 (mask-then-scale == scale-then-mask: -inf/8 = -inf)
#pragma unroll
    for (int it = 0; it < 4; ++it) {
        int f = it * 256 + tid, r = f >> 4, e = (f & 15) << 2;
        float4 v = *(const float4*)(qbase + (size_t)r * (3 * DD) + e);
        float4 w; w.x = v.x * 0.125f; w.y = v.y * 0.125f; w.z = v.z * 0.125f; w.w = v.w * 0.125f;
        *(float4*)(&Qs[r * FA_PAD + e]) = w;
    }

    float O[4][4] = {};
    float m[4], l[4];
#pragma unroll
    for (int i = 0; i < 4; ++i) { m[i] = -INFINITY; l[i] = 0.f; }

    for (int kt = 0; kt <= qt; ++kt) {
        int k0 = kt * 64;
        __syncthreads();   // prior-iter P/V reads done (also orders Q store->read on iter 0)
#pragma unroll
        for (int it = 0; it < 4; ++it) {
            int f = it * 256 + tid, r = f >> 4, e = (f & 15) << 2;
            *(float4*)(&Ks[r * FA_PAD + e]) = *(const float4*)(kbase + (size_t)(k0 + r) * (3 * DD) + e);
            *(float4*)(&Vs[r * FA_PAD + e]) = *(const float4*)(vbase + (size_t)(k0 + r) * (3 * DD) + e);
        }
        __syncthreads();

        float s[4][4] = {};
#pragma unroll
        for (int k = 0; k < 64; k += 4) {
            float4 a4[4], b4[4];
#pragma unroll
            for (int i = 0; i < 4; ++i) a4[i] = *(const float4*)(&Qs[(4 * ty + i) * FA_PAD + k]);
#pragma unroll
            for (int j = 0; j < 4; ++j) b4[j] = *(const float4*)(&Ks[(4 * tx + j) * FA_PAD + k]);
#pragma unroll
            for (int i = 0; i < 4; ++i)
#pragma unroll
                for (int j = 0; j < 4; ++j)
                    s[i][j] += a4[i].x * b4[j].x + a4[i].y * b4[j].y
                             + a4[i].z * b4[j].z + a4[i].w * b4[j].w;
        }

        if (kt == qt) {    // diagonal tile: mask k>q
#pragma unroll
            for (int i = 0; i < 4; ++i)
#pragma unroll
                for (int j = 0; j < 4; ++j)
                    if (4 * tx + j > 4 * ty + i) s[i][j] = -INFINITY;
        }

        // online softmax (row groups = 16 threads sharing ty; shuffle over lane bits 0..3)
#pragma unroll
        for (int i = 0; i < 4; ++i) {
            float mt = fmaxf(fmaxf(s[i][0], s[i][1]), fmaxf(s[i][2], s[i][3]));
#pragma unroll
            for (int off = 8; off; off >>= 1) mt = fmaxf(mt, __shfl_xor_sync(0xffffffffu, mt, off));
            float mn = fmaxf(m[i], mt);
            float alpha = expf(m[i] - mn);
            float rs = 0.f;
#pragma unroll
            for (int j = 0; j < 4; ++j) { s[i][j] = expf(s[i][j] - mn); rs += s[i][j]; }
#pragma unroll
            for (int off = 8; off; off >>= 1) rs += __shfl_xor_sync(0xffffffffu, rs, off);
            l[i] = l[i] * alpha + rs;
            m[i] = mn;
#pragma unroll
            for (int u = 0; u < 4; ++u) O[i][u] *= alpha;
        }

        __syncthreads();   // all K-tile reads done before reusing buffer for P
#pragma unroll
        for (int i = 0; i < 4; ++i) {
            float4 p4; p4.x = s[i][0]; p4.y = s[i][1]; p4.z = s[i][2]; p4.w = s[i][3];
            *(float4*)(&Ks[(4 * ty + i) * FA_PAD + 4 * tx]) = p4;
        }
        __syncthreads();

        // O += P @ V
#pragma unroll
        for (int j = 0; j < 64; j += 4) {
            float p[4][4];
#pragma unroll
            for (int i = 0; i < 4; ++i) {
                float4 t = *(const float4*)(&Ks[(4 * ty + i) * FA_PAD + j]);
                p[i][0] = t.x; p[i][1] = t.y; p[i][2] = t.z; p[i][3] = t.w;
            }
#pragma unroll
            for (int jj = 0; jj < 4; ++jj) {
                float4 vv = *(const float4*)(&Vs[(j + jj) * FA_PAD + 4 * tx]);
#pragma unroll
                for (int i = 0; i < 4; ++i) {
                    O[i][0] += p[i][jj] * vv.x;
                    O[i][1] += p[i][jj] * vv.y;
                    O[i][2] += p[i][jj] * vv.z;
                    O[i][3] += p[i][jj] * vv.w;
                }
            }
        }
    }

    // write concat layout: attn[b, s, h*64 + e]
#pragma unroll
    for (int i = 0; i < 4; ++i) {
        float inv = 1.0f / l[i];
        float4 o; o.x = O[i][0] * inv; o.y = O[i][1] * inv; o.z = O[i][2] * inv; o.w = O[i][3] * inv;
        *(float4*)(attn + ((size_t)(b * SS + q0 + 4 * ty + i)) * DD + h * DHH + 4 * tx) = o;
    }
}

// ---------------- launch ---------------------------------------------------
extern "C" void kernel_launch(void* const* d_in, const int* in_sizes, int n_in,
                              void* d_out, int out_size) {
    const float* x   = (const float*)d_in[0];
    // d_in[1] = mask: strict-upper-triangular causal mask; implemented analytically
    const float* wq  = (const float*)d_in[2];
    const float* wk  = (const float*)d_in[3];
    const float* wv  = (const float*)d_in[4];
    const float* wo  = (const float*)d_in[5];
    const float* w1  = (const float*)d_in[6];
    const float* b1  = (const float*)d_in[7];
    const float* w2  = (const float*)d_in[8];
    const float* b2  = (const float*)d_in[9];
    const float* g1  = (const float*)d_in[10];
    const float* be1 = (const float*)d_in[11];
    const float* g2  = (const float*)d_in[12];
    const float* be2 = (const float*)d_in[13];
    float* out = (float*)d_out;

    float *h, *h2, *wqkv, *qkv, *attn, *ff1;
    cudaGetSymbolAddress((void**)&h,    g_h);
    cudaGetSymbolAddress((void**)&h2,   g_h2);
    cudaGetSymbolAddress((void**)&wqkv, g_wqkv);
    cudaGetSymbolAddress((void**)&qkv,  g_qkv);
    cudaGetSymbolAddress((void**)&attn, g_attn);
    cudaGetSymbolAddress((void**)&ff1,  g_ff1);

    // 1. LN1
    ln_kernel<<<NROWS, 256>>>(x, g1, be1, h);
    // 2. pack QKV weights
    repack_wqkv<<<(DD * 3 * DD) / 256, 256>>>(wq, wk, wv, wqkv);
    // 3. QKV projection: [8192,1024] @ [1024,3072]
    sgemm_kernel<0><<<dim3(3 * DD / 128, NROWS / 128), 256>>>(h, wqkv, qkv, nullptr, nullptr,
                                                              NROWS, 3 * DD, DD);
    // 4. flash attention
    cudaFuncSetAttribute(flash_attn_kernel, cudaFuncAttributeMaxDynamicSharedMemorySize, FA_SMEM);
    flash_attn_kernel<<<dim3(SS / 64, BB * HH), 256, FA_SMEM>>>(qkv, attn);
    // 5. out = x + attn @ wo
    sgemm_kernel<1><<<dim3(DD / 128, NROWS / 128), 256>>>(attn, wo, out, nullptr, x,
                                                          NROWS, DD, DD);
    // 6. LN2 on out
    ln_kernel<<<NROWS, 256>>>(out, g2, be2, h2);
    // 7. ff1 = gelu(h2 @ w1 + b1)
    sgemm_kernel<2><<<dim3(FFD / 128, NROWS / 128), 256>>>(h2, w1, ff1, b1, nullptr,
                                                           NROWS, FFD, DD);
    // 8. out = out + ff1 @ w2 + b2   (in-place residual)
    sgemm_kernel<3><<<dim3(DD / 128, NROWS / 128), 256>>>(ff1, w2, out, b2, out,
                                                          NROWS, DD, FFD);
}

// round 4
// speedup vs baseline: 2.0170x; 2.0170x over previous
#include <cuda_runtime.h>
#include <math.h>
#include <stdint.h>

// Problem constants
#define BB 4
#define SS 2048
#define DD 1024
#define HH 16
#define DHH 64
#define FFD 4096
#define NROWS (BB*SS)          // 8192

// ---------------- scratch (device globals: allocation-guard safe) ----------
__device__ float g_h   [(size_t)NROWS * DD];        // LN1 out (tf32-rounded)
__device__ float g_h2  [(size_t)NROWS * DD];        // LN2 out (tf32-rounded)
__device__ float g_wqkv[(size_t)3 * DD * DD];       // packed [3072 (N), 1024 (K)]
__device__ float g_wot [(size_t)DD * DD];           // wo^T   [1024, 1024]
__device__ float g_w1t [(size_t)FFD * DD];          // w1^T   [4096, 1024]
__device__ float g_w2t [(size_t)DD * FFD];          // w2^T   [1024, 4096]
__device__ float g_qkv [(size_t)NROWS * 3 * DD];    // [8192, 3072] fp32
__device__ float g_attn[(size_t)NROWS * DD];        // attention out (tf32-rounded)
__device__ float g_ff1 [(size_t)NROWS * FFD];       // FFN hidden (tf32-rounded)

// ---------------- helpers ---------------------------------------------------
__device__ __forceinline__ float to_tf32(float x) {
    uint32_t u;
    asm("cvt.rna.tf32.f32 %0, %1;" : "=r"(u) : "f"(x));
    return __uint_as_float(u);
}

__device__ __forceinline__ uint32_t smem_u32(const void* p) {
    return (uint32_t)__cvta_generic_to_shared(p);
}

__device__ __forceinline__ void cp16(uint32_t dst, const void* src) {
    asm volatile("cp.async.cg.shared.global [%0], [%1], 16;" :: "r"(dst), "l"(src));
}
#define CP_COMMIT() asm volatile("cp.async.commit_group;" ::: "memory")
#define CP_WAIT1()  asm volatile("cp.async.wait_group 1;" ::: "memory")

__device__ __forceinline__ void mma_tf32(float* c, const uint32_t* a, const uint32_t* b) {
    asm volatile(
        "mma.sync.aligned.m16n8k8.row.col.f32.tf32.tf32.f32 "
        "{%0,%1,%2,%3}, {%4,%5,%6,%7}, {%8,%9}, {%0,%1,%2,%3};"
        : "+f"(c[0]), "+f"(c[1]), "+f"(c[2]), "+f"(c[3])
        : "r"(a[0]), "r"(a[1]), "r"(a[2]), "r"(a[3]), "r"(b[0]), "r"(b[1]));
}

__device__ __forceinline__ float gelu_exact(float v) {
    return 0.5f * v * (1.0f + erff(v * 0.70710678118654752f));
}

// ---------------- LayerNorm: one block (256 thr) per row of 1024 ----------
__global__ __launch_bounds__(256) void ln_kernel(const float* __restrict__ x,
                                                 const float* __restrict__ gamma,
                                                 const float* __restrict__ beta,
                                                 float* __restrict__ out) {
    __shared__ float red[8];
    __shared__ float s_mean, s_rstd;
    int row = blockIdx.x, tid = threadIdx.x;
    const float* xr = x + (size_t)row * DD;
    float4 v = *(const float4*)(xr + tid * 4);
    float s = v.x + v.y + v.z + v.w;
#pragma unroll
    for (int off = 16; off; off >>= 1) s += __shfl_xor_sync(0xffffffffu, s, off);
    if ((tid & 31) == 0) red[tid >> 5] = s;
    __syncthreads();
    if (tid == 0) {
        float t = 0.f;
#pragma unroll
        for (int i = 0; i < 8; ++i) t += red[i];
        s_mean = t * (1.0f / DD);
    }
    __syncthreads();
    float mean = s_mean;
    float dx = v.x - mean, dy = v.y - mean, dz = v.z - mean, dw = v.w - mean;
    float sq = dx*dx + dy*dy + dz*dz + dw*dw;
#pragma unroll
    for (int off = 16; off; off >>= 1) sq += __shfl_xor_sync(0xffffffffu, sq, off);
    if ((tid & 31) == 0) red[tid >> 5] = sq;
    __syncthreads();
    if (tid == 0) {
        float t = 0.f;
#pragma unroll
        for (int i = 0; i < 8; ++i) t += red[i];
        s_rstd = rsqrtf(t * (1.0f / DD) + 1e-5f);
    }
    __syncthreads();
    float rstd = s_rstd;
    float4 g4 = *(const float4*)(gamma + tid * 4);
    float4 b4 = *(const float4*)(beta + tid * 4);
    float4 o;
    o.x = to_tf32(dx * rstd * g4.x + b4.x);
    o.y = to_tf32(dy * rstd * g4.y + b4.y);
    o.z = to_tf32(dz * rstd * g4.z + b4.z);
    o.w = to_tf32(dw * rstd * g4.w + b4.w);
    *(float4*)(out + (size_t)row * DD + tid * 4) = o;
}

// ---------------- pack wq/wk/wv [H,D,DH] -> [3072 (N), 1024 (K)] ----------
__global__ __launch_bounds__(256) void repack_wqkv(const float* __restrict__ wq,
                                                   const float* __restrict__ wk,
                                                   const float* __restrict__ wv,
                                                   float* __restrict__ wt) {
    int idx = blockIdx.x * 256 + threadIdx.x;      // over 3072*1024
    int n = idx >> 10;            // output row (N)
    int d = idx & 1023;           // output col (K)
    int part = n >> 10;           // 0:q 1:k 2:v
    int c = n & 1023;
    int h = c >> 6, e = c & 63;
    const float* w = (part == 0) ? wq : (part == 1) ? wk : wv;
    wt[idx] = to_tf32(w[((size_t)h * DD + d) * DHH + e]);
}

// ---------------- transpose [R,C] -> [C,R] with tf32 rounding -------------
__global__ __launch_bounds__(256) void transpose_kernel(const float* __restrict__ in,
                                                        float* __restrict__ out,
                                                        int R, int C) {
    __shared__ float t[32][33];
    int rb = blockIdx.y * 32, cb = blockIdx.x * 32;
#pragma unroll
    for (int i = 0; i < 32; i += 8)
        t[threadIdx.y + i][threadIdx.x] = in[(size_t)(rb + threadIdx.y + i) * C + cb + threadIdx.x];
    __syncthreads();
#pragma unroll
    for (int i = 0; i < 32; i += 8)
        out[(size_t)(cb + threadIdx.y + i) * R + rb + threadIdx.x] =
            to_tf32(t[threadIdx.x][threadIdx.y + i]);
}

// ---------------- tf32 mma.sync GEMM: C[M,N] = A[M,K] @ Wt[N,K]^T ---------
// EPI 0: none   1: +res   2: +bias, gelu, tf32-round   3: +bias +res
// CTA tile 128x128, BK=16, 8 warps (2x4), warp tile 64x32 (4x4 m16n8k8).
// Smem per stage: A[128][20] + B[128][20] floats (pad 20 -> conflict-free frags).
#define BK 16
#define APAD 20
#define HALF_FLOATS (128 * APAD)                  // 2560
#define STAGE_FLOATS (2 * HALF_FLOATS)            // 5120
#define NSTG 3
#define GEMM_SMEM (NSTG * STAGE_FLOATS * 4)       // 61440 bytes

template<int EPI>
__global__ __launch_bounds__(256)
void gemm_tc_kernel(const float* __restrict__ A, const float* __restrict__ Wt,
                    float* __restrict__ C,
                    const float* __restrict__ bias, const float* __restrict__ res,
                    int M, int N, int K) {
    extern __shared__ float smem[];
    uint32_t sbase = smem_u32(smem);
    int tid = threadIdx.x;
    int wid = tid >> 5, lane = tid & 31;
    int g = lane >> 2, t = lane & 3;               // groupID, thread-in-group
    int warp_m = wid >> 2, warp_n = wid & 3;       // 2 x 4
    int m0 = blockIdx.y << 7, n0 = blockIdx.x << 7;

    const float* Ab = A + (size_t)m0 * K;
    const float* Bb = Wt + (size_t)n0 * K;
    int kt = K >> 4;                               // BK=16 tiles

    float acc[4][4][4] = {};

    // ---- async load of one k-tile into stage s ----
    auto load_stage = [&](int s, int jt) {
        uint32_t sA = sbase + s * STAGE_FLOATS * 4;
        uint32_t sB = sA + HALF_FLOATS * 4;
        int k0 = jt << 4;
#pragma unroll
        for (int i = 0; i < 2; ++i) {
            int f = i * 256 + tid;                 // 0..511
            int row = f >> 2, ch = f & 3;
            uint32_t doff = (uint32_t)(row * (APAD * 4) + ch * 16);
            cp16(sA + doff, Ab + (size_t)row * K + k0 + ch * 4);
            cp16(sB + doff, Bb + (size_t)row * K + k0 + ch * 4);
        }
    };

    // prologue: stages 0..NSTG-2
#pragma unroll
    for (int s = 0; s < NSTG - 1; ++s) { load_stage(s, s); CP_COMMIT(); }

    for (int j = 0; j < kt; ++j) {
        CP_WAIT1();
        __syncthreads();
        const float* As = smem + (j % NSTG) * STAGE_FLOATS;
        const float* Bs = As + HALF_FLOATS;
#pragma unroll
        for (int ks = 0; ks < 2; ++ks) {
            int kb = ks * 8;
            uint32_t a[4][4], b[4][2];
#pragma unroll
            for (int mt = 0; mt < 4; ++mt) {
                int mrow = warp_m * 64 + mt * 16;
                a[mt][0] = __float_as_uint(As[(mrow + g)     * APAD + kb + t]);
                a[mt][1] = __float_as_uint(As[(mrow + g + 8) * APAD + kb + t]);
                a[mt][2] = __float_as_uint(As[(mrow + g)     * APAD + kb + t + 4]);
                a[mt][3] = __float_as_uint(As[(mrow + g + 8) * APAD + kb + t + 4]);
            }
#pragma unroll
            for (int nt = 0; nt < 4; ++nt) {
                int nrow = warp_n * 32 + nt * 8;
                b[nt][0] = __float_as_uint(Bs[(nrow + g) * APAD + kb + t]);
                b[nt][1] = __float_as_uint(Bs[(nrow + g) * APAD + kb + t + 4]);
            }
#pragma unroll
            for (int mt = 0; mt < 4; ++mt)
#pragma unroll
                for (int nt = 0; nt < 4; ++nt)
                    mma_tf32(acc[mt][nt], a[mt], b[nt]);
        }
        // next load (must come after all warps finished reading the stage it
        // overwrites — guaranteed by the barrier at the top of the NEXT iter,
        // which follows this iteration's compute in program order)
        if (j + NSTG - 1 < kt) load_stage((j + NSTG - 1) % NSTG, j + NSTG - 1);
        CP_COMMIT();
    }

    // ---- epilogue: registers -> global (float2 per c-pair) ----
#pragma unroll
    for (int mt = 0; mt < 4; ++mt) {
#pragma unroll
        for (int nt = 0; nt < 4; ++nt) {
#pragma unroll
            for (int half = 0; half < 2; ++half) {
                int row = m0 + warp_m * 64 + mt * 16 + g + half * 8;
                int col = n0 + warp_n * 32 + nt * 8 + 2 * t;
                float v0 = acc[mt][nt][half * 2 + 0];
                float v1 = acc[mt][nt][half * 2 + 1];
                size_t ga = (size_t)row * N + col;
                if (EPI == 1) {
                    float2 r = *(const float2*)(res + ga);
                    v0 += r.x; v1 += r.y;
                } else if (EPI == 2) {
                    v0 = to_tf32(gelu_exact(v0 + bias[col]));
                    v1 = to_tf32(gelu_exact(v1 + bias[col + 1]));
                } else if (EPI == 3) {
                    float2 r = *(const float2*)(res + ga);
                    v0 += bias[col] + r.x; v1 += bias[col + 1] + r.y;
                }
                float2 o; o.x = v0; o.y = v1;
                *(float2*)(C + ga) = o;
            }
        }
    }
}

// ---------------- Flash attention (causal), fp32, DH=64 -------------------
#define FA_PAD 68
#define FA_SMEM (3 * 64 * FA_PAD * 4)

__global__ __launch_bounds__(256) void flash_attn_kernel(const float* __restrict__ qkv,
                                                         float* __restrict__ attn) {
    extern __shared__ float sm[];
    float* Qs = sm;
    float* Ks = sm + 64 * FA_PAD;
    float* Vs = sm + 2 * 64 * FA_PAD;
    int tid = threadIdx.x;
    int ty = tid >> 4, tx = tid & 15;
    int qt = blockIdx.x;
    int b = blockIdx.y >> 4, h = blockIdx.y & 15;
    int q0 = qt * 64;
    const float* qbase = qkv + ((size_t)(b * SS + q0)) * (3 * DD) + h * DHH;
    const float* kbase = qkv + ((size_t)(b * SS)) * (3 * DD) + DD + h * DHH;
    const float* vbase = qkv + ((size_t)(b * SS)) * (3 * DD) + 2 * DD + h * DHH;

#pragma unroll
    for (int it = 0; it < 4; ++it) {
        int f = it * 256 + tid, r = f >> 4, e = (f & 15) << 2;
        float4 v = *(const float4*)(qbase + (size_t)r * (3 * DD) + e);
        float4 w; w.x = v.x * 0.125f; w.y = v.y * 0.125f; w.z = v.z * 0.125f; w.w = v.w * 0.125f;
        *(float4*)(&Qs[r * FA_PAD + e]) = w;
    }

    float O[4][4] = {};
    float m[4], l[4];
#pragma unroll
    for (int i = 0; i < 4; ++i) { m[i] = -INFINITY; l[i] = 0.f; }

    for (int kt = 0; kt <= qt; ++kt) {
        int k0 = kt * 64;
        __syncthreads();
#pragma unroll
        for (int it = 0; it < 4; ++it) {
            int f = it * 256 + tid, r = f >> 4, e = (f & 15) << 2;
            *(float4*)(&Ks[r * FA_PAD + e]) = *(const float4*)(kbase + (size_t)(k0 + r) * (3 * DD) + e);
            *(float4*)(&Vs[r * FA_PAD + e]) = *(const float4*)(vbase + (size_t)(k0 + r) * (3 * DD) + e);
        }
        __syncthreads();

        float s[4][4] = {};
#pragma unroll
        for (int k = 0; k < 64; k += 4) {
            float4 a4[4], b4[4];
#pragma unroll
            for (int i = 0; i < 4; ++i) a4[i] = *(const float4*)(&Qs[(4 * ty + i) * FA_PAD + k]);
#pragma unroll
            for (int j = 0; j < 4; ++j) b4[j] = *(const float4*)(&Ks[(4 * tx + j) * FA_PAD + k]);
#pragma unroll
            for (int i = 0; i < 4; ++i)
#pragma unroll
                for (int j = 0; j < 4; ++j)
                    s[i][j] += a4[i].x * b4[j].x + a4[i].y * b4[j].y
                             + a4[i].z * b4[j].z + a4[i].w * b4[j].w;
        }

        if (kt == qt) {
#pragma unroll
            for (int i = 0; i < 4; ++i)
#pragma unroll
                for (int j = 0; j < 4; ++j)
                    if (4 * tx + j > 4 * ty + i) s[i][j] = -INFINITY;
        }

#pragma unroll
        for (int i = 0; i < 4; ++i) {
            float mt = fmaxf(fmaxf(s[i][0], s[i][1]), fmaxf(s[i][2], s[i][3]));
#pragma unroll
            for (int off = 8; off; off >>= 1) mt = fmaxf(mt, __shfl_xor_sync(0xffffffffu, mt, off));
            float mn = fmaxf(m[i], mt);
            float alpha = expf(m[i] - mn);
            float rs = 0.f;
#pragma unroll
            for (int j = 0; j < 4; ++j) { s[i][j] = expf(s[i][j] - mn); rs += s[i][j]; }
#pragma unroll
            for (int off = 8; off; off >>= 1) rs += __shfl_xor_sync(0xffffffffu, rs, off);
            l[i] = l[i] * alpha + rs;
            m[i] = mn;
#pragma unroll
            for (int u = 0; u < 4; ++u) O[i][u] *= alpha;
        }

        __syncthreads();
#pragma unroll
        for (int i = 0; i < 4; ++i) {
            float4 p4; p4.x = s[i][0]; p4.y = s[i][1]; p4.z = s[i][2]; p4.w = s[i][3];
            *(float4*)(&Ks[(4 * ty + i) * FA_PAD + 4 * tx]) = p4;
        }
        __syncthreads();

#pragma unroll
        for (int j = 0; j < 64; j += 4) {
            float p[4][4];
#pragma unroll
            for (int i = 0; i < 4; ++i) {
                float4 tt = *(const float4*)(&Ks[(4 * ty + i) * FA_PAD + j]);
                p[i][0] = tt.x; p[i][1] = tt.y; p[i][2] = tt.z; p[i][3] = tt.w;
            }
#pragma unroll
            for (int jj = 0; jj < 4; ++jj) {
                float4 vv = *(const float4*)(&Vs[(j + jj) * FA_PAD + 4 * tx]);
#pragma unroll
                for (int i = 0; i < 4; ++i) {
                    O[i][0] += p[i][jj] * vv.x;
                    O[i][1] += p[i][jj] * vv.y;
                    O[i][2] += p[i][jj] * vv.z;
                    O[i][3] += p[i][jj] * vv.w;
                }
            }
        }
    }

#pragma unroll
    for (int i = 0; i < 4; ++i) {
        float inv = 1.0f / l[i];
        float4 o;
        o.x = to_tf32(O[i][0] * inv); o.y = to_tf32(O[i][1] * inv);
        o.z = to_tf32(O[i][2] * inv); o.w = to_tf32(O[i][3] * inv);
        *(float4*)(attn + ((size_t)(b * SS + q0 + 4 * ty + i)) * DD + h * DHH + 4 * tx) = o;
    }
}

// ---------------- launch ---------------------------------------------------
extern "C" void kernel_launch(void* const* d_in, const int* in_sizes, int n_in,
                              void* d_out, int out_size) {
    const float* x   = (const float*)d_in[0];
    const float* wq  = (const float*)d_in[2];
    const float* wk  = (const float*)d_in[3];
    const float* wv  = (const float*)d_in[4];
    const float* wo  = (const float*)d_in[5];
    const float* w1  = (const float*)d_in[6];
    const float* b1  = (const float*)d_in[7];
    const float* w2  = (const float*)d_in[8];
    const float* b2  = (const float*)d_in[9];
    const float* g1  = (const float*)d_in[10];
    const float* be1 = (const float*)d_in[11];
    const float* g2  = (const float*)d_in[12];
    const float* be2 = (const float*)d_in[13];
    float* out = (float*)d_out;

    float *h, *h2, *wqkv, *wot, *w1t, *w2t, *qkv, *attn, *ff1;
    cudaGetSymbolAddress((void**)&h,    g_h);
    cudaGetSymbolAddress((void**)&h2,   g_h2);
    cudaGetSymbolAddress((void**)&wqkv, g_wqkv);
    cudaGetSymbolAddress((void**)&wot,  g_wot);
    cudaGetSymbolAddress((void**)&w1t,  g_w1t);
    cudaGetSymbolAddress((void**)&w2t,  g_w2t);
    cudaGetSymbolAddress((void**)&qkv,  g_qkv);
    cudaGetSymbolAddress((void**)&attn, g_attn);
    cudaGetSymbolAddress((void**)&ff1,  g_ff1);

    cudaFuncSetAttribute(gemm_tc_kernel<0>, cudaFuncAttributeMaxDynamicSharedMemorySize, GEMM_SMEM);
    cudaFuncSetAttribute(gemm_tc_kernel<1>, cudaFuncAttributeMaxDynamicSharedMemorySize, GEMM_SMEM);
    cudaFuncSetAttribute(gemm_tc_kernel<2>, cudaFuncAttributeMaxDynamicSharedMemorySize, GEMM_SMEM);
    cudaFuncSetAttribute(gemm_tc_kernel<3>, cudaFuncAttributeMaxDynamicSharedMemorySize, GEMM_SMEM);
    cudaFuncSetAttribute(flash_attn_kernel, cudaFuncAttributeMaxDynamicSharedMemorySize, FA_SMEM);

    // weight repacks (per-launch; ~25us total)
    repack_wqkv<<<(3 * DD * DD) / 256, 256>>>(wq, wk, wv, wqkv);
    transpose_kernel<<<dim3(DD / 32, DD / 32),  dim3(32, 8)>>>(wo, wot, DD, DD);
    transpose_kernel<<<dim3(FFD / 32, DD / 32), dim3(32, 8)>>>(w1, w1t, DD, FFD);
    transpose_kernel<<<dim3(DD / 32, FFD / 32), dim3(32, 8)>>>(w2, w2t, FFD, DD);

    // 1. LN1 (tf32-rounded output)
    ln_kernel<<<NROWS, 256>>>(x, g1, be1, h);
    // 2. QKV projection: [8192,1024] @ [1024,3072]
    gemm_tc_kernel<0><<<dim3(3 * DD / 128, NROWS / 128), 256, GEMM_SMEM>>>(
        h, wqkv, qkv, nullptr, nullptr, NROWS, 3 * DD, DD);
    // 3. flash attention
    flash_attn_kernel<<<dim3(SS / 64, BB * HH), 256, FA_SMEM>>>(qkv, attn);
    // 4. out = x + attn @ wo
    gemm_tc_kernel<1><<<dim3(DD / 128, NROWS / 128), 256, GEMM_SMEM>>>(
        attn, wot, out, nullptr, x, NROWS, DD, DD);
    // 5. LN2
    ln_kernel<<<NROWS, 256>>>(out, g2, be2, h2);
    // 6. ff1 = gelu(h2 @ w1 + b1)  (tf32-rounded)
    gemm_tc_kernel<2><<<dim3(FFD / 128, NROWS / 128), 256, GEMM_SMEM>>>(
        h2, w1t, ff1, b1, nullptr, NROWS, FFD, DD);
    // 7. out = out + ff1 @ w2 + b2
    gemm_tc_kernel<3><<<dim3(DD / 128, NROWS / 128), 256, GEMM_SMEM>>>(
        ff1, w2t, out, b2, out, NROWS, DD, FFD);
}

// round 5
// speedup vs baseline: 3.4943x; 1.7325x over previous
#include <cuda_runtime.h>
#include <math.h>
#include <stdint.h>

// Problem constants
#define BB 4
#define SS 2048
#define DD 1024
#define HH 16
#define DHH 64
#define FFD 4096
#define NROWS (BB*SS)          // 8192

// ---------------- scratch (device globals: allocation-guard safe) ----------
__device__ float g_h   [(size_t)NROWS * DD];        // LN1 out (tf32-rounded)
__device__ float g_h2  [(size_t)NROWS * DD];        // LN2 out (tf32-rounded)
__device__ float g_wqkv[(size_t)3 * DD * DD];       // packed [3072 (N), 1024 (K)]
__device__ float g_wot [(size_t)DD * DD];           // wo^T   [1024, 1024]
__device__ float g_w1t [(size_t)FFD * DD];          // w1^T   [4096, 1024]
__device__ float g_w2t [(size_t)DD * FFD];          // w2^T   [1024, 4096]
__device__ float g_qkv [(size_t)NROWS * 3 * DD];    // [8192, 3072] fp32
__device__ float g_attn[(size_t)NROWS * DD];        // attention out (tf32-rounded)
__device__ float g_ff1 [(size_t)NROWS * FFD];       // FFN hidden (tf32-rounded)

// ---------------- helpers ---------------------------------------------------
__device__ __forceinline__ float to_tf32(float x) {
    uint32_t u;
    asm("cvt.rna.tf32.f32 %0, %1;" : "=r"(u) : "f"(x));
    return __uint_as_float(u);
}

__device__ __forceinline__ uint32_t smem_u32(const void* p) {
    return (uint32_t)__cvta_generic_to_shared(p);
}

__device__ __forceinline__ void cp16(uint32_t dst, const void* src) {
    asm volatile("cp.async.cg.shared.global [%0], [%1], 16;" :: "r"(dst), "l"(src));
}
#define CP_COMMIT() asm volatile("cp.async.commit_group;" ::: "memory")
#define CP_WAIT1()  asm volatile("cp.async.wait_group 1;" ::: "memory")

__device__ __forceinline__ void mma_tf32(float* c, const uint32_t* a, const uint32_t* b) {
    asm volatile(
        "mma.sync.aligned.m16n8k8.row.col.f32.tf32.tf32.f32 "
        "{%0,%1,%2,%3}, {%4,%5,%6,%7}, {%8,%9}, {%0,%1,%2,%3};"
        : "+f"(c[0]), "+f"(c[1]), "+f"(c[2]), "+f"(c[3])
        : "r"(a[0]), "r"(a[1]), "r"(a[2]), "r"(a[3]), "r"(b[0]), "r"(b[1]));
}

__device__ __forceinline__ float gelu_exact(float v) {
    return 0.5f * v * (1.0f + erff(v * 0.70710678118654752f));
}

// ---------------- LayerNorm: one block (256 thr) per row of 1024 ----------
__global__ __launch_bounds__(256) void ln_kernel(const float* __restrict__ x,
                                                 const float* __restrict__ gamma,
                                                 const float* __restrict__ beta,
                                                 float* __restrict__ out) {
    __shared__ float red[8];
    __shared__ float s_mean, s_rstd;
    int row = blockIdx.x, tid = threadIdx.x;
    const float* xr = x + (size_t)row * DD;
    float4 v = *(const float4*)(xr + tid * 4);
    float s = v.x + v.y + v.z + v.w;
#pragma unroll
    for (int off = 16; off; off >>= 1) s += __shfl_xor_sync(0xffffffffu, s, off);
    if ((tid & 31) == 0) red[tid >> 5] = s;
    __syncthreads();
    if (tid == 0) {
        float t = 0.f;
#pragma unroll
        for (int i = 0; i < 8; ++i) t += red[i];
        s_mean = t * (1.0f / DD);
    }
    __syncthreads();
    float mean = s_mean;
    float dx = v.x - mean, dy = v.y - mean, dz = v.z - mean, dw = v.w - mean;
    float sq = dx*dx + dy*dy + dz*dz + dw*dw;
#pragma unroll
    for (int off = 16; off; off >>= 1) sq += __shfl_xor_sync(0xffffffffu, sq, off);
    if ((tid & 31) == 0) red[tid >> 5] = sq;
    __syncthreads();
    if (tid == 0) {
        float t = 0.f;
#pragma unroll
        for (int i = 0; i < 8; ++i) t += red[i];
        s_rstd = rsqrtf(t * (1.0f / DD) + 1e-5f);
    }
    __syncthreads();
    float rstd = s_rstd;
    float4 g4 = *(const float4*)(gamma + tid * 4);
    float4 b4 = *(const float4*)(beta + tid * 4);
    float4 o;
    o.x = to_tf32(dx * rstd * g4.x + b4.x);
    o.y = to_tf32(dy * rstd * g4.y + b4.y);
    o.z = to_tf32(dz * rstd * g4.z + b4.z);
    o.w = to_tf32(dw * rstd * g4.w + b4.w);
    *(float4*)(out + (size_t)row * DD + tid * 4) = o;
}

// ---------------- pack wq/wk/wv [H,D,DH] -> [3072 (N), 1024 (K)] ----------
__global__ __launch_bounds__(256) void repack_wqkv(const float* __restrict__ wq,
                                                   const float* __restrict__ wk,
                                                   const float* __restrict__ wv,
                                                   float* __restrict__ wt) {
    int idx = blockIdx.x * 256 + threadIdx.x;      // over 3072*1024
    int n = idx >> 10;            // output row (N)
    int d = idx & 1023;           // output col (K)
    int part = n >> 10;           // 0:q 1:k 2:v
    int c = n & 1023;
    int h = c >> 6, e = c & 63;
    const float* w = (part == 0) ? wq : (part == 1) ? wk : wv;
    wt[idx] = to_tf32(w[((size_t)h * DD + d) * DHH + e]);
}

// ---------------- transpose [R,C] -> [C,R] with tf32 rounding -------------
__global__ __launch_bounds__(256) void transpose_kernel(const float* __restrict__ in,
                                                        float* __restrict__ out,
                                                        int R, int C) {
    __shared__ float t[32][33];
    int rb = blockIdx.y * 32, cb = blockIdx.x * 32;
#pragma unroll
    for (int i = 0; i < 32; i += 8)
        t[threadIdx.y + i][threadIdx.x] = in[(size_t)(rb + threadIdx.y + i) * C + cb + threadIdx.x];
    __syncthreads();
#pragma unroll
    for (int i = 0; i < 32; i += 8)
        out[(size_t)(cb + threadIdx.y + i) * R + rb + threadIdx.x] =
            to_tf32(t[threadIdx.x][threadIdx.y + i]);
}

// ---------------- tf32 mma.sync GEMM: C[M,N] = A[M,K] @ Wt[N,K]^T ---------
// EPI 0: none   1: +res   2: +bias, gelu, tf32-round   3: +bias +res
#define BK 16
#define APAD 20
#define HALF_FLOATS (128 * APAD)                  // 2560
#define STAGE_FLOATS (2 * HALF_FLOATS)            // 5120
#define NSTG 3
#define GEMM_SMEM (NSTG * STAGE_FLOATS * 4)       // 61440 bytes

template<int EPI>
__global__ __launch_bounds__(256)
void gemm_tc_kernel(const float* __restrict__ A, const float* __restrict__ Wt,
                    float* __restrict__ C,
                    const float* __restrict__ bias, const float* __restrict__ res,
                    int M, int N, int K) {
    extern __shared__ float smem[];
    uint32_t sbase = smem_u32(smem);
    int tid = threadIdx.x;
    int wid = tid >> 5, lane = tid & 31;
    int g = lane >> 2, t = lane & 3;
    int warp_m = wid >> 2, warp_n = wid & 3;
    int m0 = blockIdx.y << 7, n0 = blockIdx.x << 7;

    const float* Ab = A + (size_t)m0 * K;
    const float* Bb = Wt + (size_t)n0 * K;
    int kt = K >> 4;

    float acc[4][4][4] = {};

    auto load_stage = [&](int s, int jt) {
        uint32_t sA = sbase + s * STAGE_FLOATS * 4;
        uint32_t sB = sA + HALF_FLOATS * 4;
        int k0 = jt << 4;
#pragma unroll
        for (int i = 0; i < 2; ++i) {
            int f = i * 256 + tid;
            int row = f >> 2, ch = f & 3;
            uint32_t doff = (uint32_t)(row * (APAD * 4) + ch * 16);
            cp16(sA + doff, Ab + (size_t)row * K + k0 + ch * 4);
            cp16(sB + doff, Bb + (size_t)row * K + k0 + ch * 4);
        }
    };

#pragma unroll
    for (int s = 0; s < NSTG - 1; ++s) { load_stage(s, s); CP_COMMIT(); }

    for (int j = 0; j < kt; ++j) {
        CP_WAIT1();
        __syncthreads();
        const float* As = smem + (j % NSTG) * STAGE_FLOATS;
        const float* Bs = As + HALF_FLOATS;
#pragma unroll
        for (int ks = 0; ks < 2; ++ks) {
            int kb = ks * 8;
            uint32_t a[4][4], b[4][2];
#pragma unroll
            for (int mt = 0; mt < 4; ++mt) {
                int mrow = warp_m * 64 + mt * 16;
                a[mt][0] = __float_as_uint(As[(mrow + g)     * APAD + kb + t]);
                a[mt][1] = __float_as_uint(As[(mrow + g + 8) * APAD + kb + t]);
                a[mt][2] = __float_as_uint(As[(mrow + g)     * APAD + kb + t + 4]);
                a[mt][3] = __float_as_uint(As[(mrow + g + 8) * APAD + kb + t + 4]);
            }
#pragma unroll
            for (int nt = 0; nt < 4; ++nt) {
                int nrow = warp_n * 32 + nt * 8;
                b[nt][0] = __float_as_uint(Bs[(nrow + g) * APAD + kb + t]);
                b[nt][1] = __float_as_uint(Bs[(nrow + g) * APAD + kb + t + 4]);
            }
#pragma unroll
            for (int mt = 0; mt < 4; ++mt)
#pragma unroll
                for (int nt = 0; nt < 4; ++nt)
                    mma_tf32(acc[mt][nt], a[mt], b[nt]);
        }
        if (j + NSTG - 1 < kt) load_stage((j + NSTG - 1) % NSTG, j + NSTG - 1);
        CP_COMMIT();
    }

#pragma unroll
    for (int mt = 0; mt < 4; ++mt) {
#pragma unroll
        for (int nt = 0; nt < 4; ++nt) {
#pragma unroll
            for (int half = 0; half < 2; ++half) {
                int row = m0 + warp_m * 64 + mt * 16 + g + half * 8;
                int col = n0 + warp_n * 32 + nt * 8 + 2 * t;
                float v0 = acc[mt][nt][half * 2 + 0];
                float v1 = acc[mt][nt][half * 2 + 1];
                size_t ga = (size_t)row * N + col;
                if (EPI == 1) {
                    float2 r = *(const float2*)(res + ga);
                    v0 += r.x; v1 += r.y;
                } else if (EPI == 2) {
                    v0 = to_tf32(gelu_exact(v0 + bias[col]));
                    v1 = to_tf32(gelu_exact(v1 + bias[col + 1]));
                } else if (EPI == 3) {
                    float2 r = *(const float2*)(res + ga);
                    v0 += bias[col] + r.x; v1 += bias[col + 1] + r.y;
                }
                float2 o; o.x = v0; o.y = v1;
                *(float2*)(C + ga) = o;
            }
        }
    }
}

// ---------------- Flash attention (causal) with tf32 mma.sync -------------
// CTA: 128 q-rows for one (b,h). 8 warps, warp w owns q-rows [w*16, w*16+16).
// K-tiles of 64 keys. Q staged in smem once; K/V staged per tile.
// Smem: Qs[128][68], Ks[64][68] ([key][dh]), Vs[64][72] ([key][dh]).
#define QS_OFF 0
#define KS_OFF (128 * 68)                     // 8704
#define VS_OFF (KS_OFF + 64 * 68)             // 13056
#define FA_SMEM ((VS_OFF + 64 * 72) * 4)      // 70656 bytes

__global__ __launch_bounds__(256) void flash_attn_mma_kernel(const float* __restrict__ qkv,
                                                             float* __restrict__ attn) {
    extern __shared__ float sm[];
    float* Qs = sm + QS_OFF;
    float* Ks = sm + KS_OFF;
    float* Vs = sm + VS_OFF;
    int tid = threadIdx.x;
    int wid = tid >> 5, lane = tid & 31;
    int g = lane >> 2, t = lane & 3;
    int qt = blockIdx.x;
    int b = blockIdx.y >> 4, h = blockIdx.y & 15;
    int q0 = qt * 128;
    const float* qbase = qkv + ((size_t)(b * SS + q0)) * (3 * DD) + h * DHH;
    const float* kbase = qkv + ((size_t)(b * SS)) * (3 * DD) + DD + h * DHH;
    const float* vbase = qkv + ((size_t)(b * SS)) * (3 * DD) + 2 * DD + h * DHH;

    // stage Q (scaled by 1/sqrt(64)=0.125, tf32-rounded)
#pragma unroll
    for (int it = 0; it < 8; ++it) {
        int f = it * 256 + tid, r = f >> 4, e = (f & 15) << 2;
        float4 v = *(const float4*)(qbase + (size_t)r * (3 * DD) + e);
        float4 w;
        w.x = to_tf32(v.x * 0.125f); w.y = to_tf32(v.y * 0.125f);
        w.z = to_tf32(v.z * 0.125f); w.w = to_tf32(v.w * 0.125f);
        *(float4*)(&Qs[r * 68 + e]) = w;
    }

    float acc_o[8][4] = {};
    float m0r = -INFINITY, m1r = -INFINITY, l0r = 0.f, l1r = 0.f;
    int mrow = wid * 16;
    int ntiles = 2 * qt + 2;                   // keys [0, q0+128)

    for (int kt = 0; kt < ntiles; ++kt) {
        __syncthreads();                       // prior-iter K/V reads done (+ Q store on iter 0)
#pragma unroll
        for (int it = 0; it < 4; ++it) {
            int f = it * 256 + tid, r = f >> 4, e = (f & 15) << 2;
            const float* kp = kbase + (size_t)(kt * 64 + r) * (3 * DD) + e;
            const float* vp = vbase + (size_t)(kt * 64 + r) * (3 * DD) + e;
            float4 kv = *(const float4*)kp;
            float4 vv = *(const float4*)vp;
            float4 kw, vw;
            kw.x = to_tf32(kv.x); kw.y = to_tf32(kv.y); kw.z = to_tf32(kv.z); kw.w = to_tf32(kv.w);
            vw.x = to_tf32(vv.x); vw.y = to_tf32(vv.y); vw.z = to_tf32(vv.z); vw.w = to_tf32(vv.w);
            *(float4*)(&Ks[r * 68 + e]) = kw;
            *(float4*)(&Vs[r * 72 + e]) = vw;
        }
        __syncthreads();

        // ---- S = Q @ K^T  (A: Qs rows, B: Ks as [n=key][k=dh]) ----
        float acc_s[8][4] = {};
#pragma unroll
        for (int ks = 0; ks < 8; ++ks) {
            int kb = ks * 8;
            uint32_t aq[4];
            aq[0] = __float_as_uint(Qs[(mrow + g)     * 68 + kb + t]);
            aq[1] = __float_as_uint(Qs[(mrow + g + 8) * 68 + kb + t]);
            aq[2] = __float_as_uint(Qs[(mrow + g)     * 68 + kb + t + 4]);
            aq[3] = __float_as_uint(Qs[(mrow + g + 8) * 68 + kb + t + 4]);
#pragma unroll
            for (int nt = 0; nt < 8; ++nt) {
                uint32_t bk[2];
                bk[0] = __float_as_uint(Ks[(nt * 8 + g) * 68 + kb + t]);
                bk[1] = __float_as_uint(Ks[(nt * 8 + g) * 68 + kb + t + 4]);
                mma_tf32(acc_s[nt], aq, bk);
            }
        }

        // ---- causal mask (only tiles that can cross the diagonal) ----
        if (kt >= 2 * qt) {
            int r0 = q0 + mrow + g, r1 = r0 + 8;
#pragma unroll
            for (int nt = 0; nt < 8; ++nt) {
                int c0 = kt * 64 + nt * 8 + 2 * t;
                if (c0     > r0) acc_s[nt][0] = -INFINITY;
                if (c0 + 1 > r0) acc_s[nt][1] = -INFINITY;
                if (c0     > r1) acc_s[nt][2] = -INFINITY;
                if (c0 + 1 > r1) acc_s[nt][3] = -INFINITY;
            }
        }

        // ---- online softmax (rows g and g+8; reduce over quad lanes) ----
        float mx0 = -INFINITY, mx1 = -INFINITY;
#pragma unroll
        for (int nt = 0; nt < 8; ++nt) {
            mx0 = fmaxf(mx0, fmaxf(acc_s[nt][0], acc_s[nt][1]));
            mx1 = fmaxf(mx1, fmaxf(acc_s[nt][2], acc_s[nt][3]));
        }
        mx0 = fmaxf(mx0, __shfl_xor_sync(0xffffffffu, mx0, 1));
        mx0 = fmaxf(mx0, __shfl_xor_sync(0xffffffffu, mx0, 2));
        mx1 = fmaxf(mx1, __shfl_xor_sync(0xffffffffu, mx1, 1));
        mx1 = fmaxf(mx1, __shfl_xor_sync(0xffffffffu, mx1, 2));
        float mn0 = fmaxf(m0r, mx0), mn1 = fmaxf(m1r, mx1);
        float al0 = __expf(m0r - mn0), al1 = __expf(m1r - mn1);
        float rs0 = 0.f, rs1 = 0.f;
#pragma unroll
        for (int nt = 0; nt < 8; ++nt) {
            acc_s[nt][0] = __expf(acc_s[nt][0] - mn0);
            acc_s[nt][1] = __expf(acc_s[nt][1] - mn0);
            acc_s[nt][2] = __expf(acc_s[nt][2] - mn1);
            acc_s[nt][3] = __expf(acc_s[nt][3] - mn1);
            rs0 += acc_s[nt][0] + acc_s[nt][1];
            rs1 += acc_s[nt][2] + acc_s[nt][3];
        }
        rs0 += __shfl_xor_sync(0xffffffffu, rs0, 1);
        rs0 += __shfl_xor_sync(0xffffffffu, rs0, 2);
        rs1 += __shfl_xor_sync(0xffffffffu, rs1, 1);
        rs1 += __shfl_xor_sync(0xffffffffu, rs1, 2);
        l0r = l0r * al0 + rs0;  m0r = mn0;
        l1r = l1r * al1 + rs1;  m1r = mn1;
#pragma unroll
        for (int nt = 0; nt < 8; ++nt) {
            acc_o[nt][0] *= al0; acc_o[nt][1] *= al0;
            acc_o[nt][2] *= al1; acc_o[nt][3] *= al1;
        }

        // ---- O += P @ V ----
        // P accumulator cols (2t, 2t+1) -> A-frag cols (t, t+4) via quad shuffles.
        int base = lane & ~3;
        int srcA = base | (t >> 1);            // col t
        int srcB = srcA + 2;                   // col t+4
        int par = t & 1;
#pragma unroll
        for (int ks = 0; ks < 8; ++ks) {
            float v00 = __shfl_sync(0xffffffffu, acc_s[ks][0], srcA);
            float v01 = __shfl_sync(0xffffffffu, acc_s[ks][1], srcA);
            float v02 = __shfl_sync(0xffffffffu, acc_s[ks][0], srcB);
            float v03 = __shfl_sync(0xffffffffu, acc_s[ks][1], srcB);
            float v10 = __shfl_sync(0xffffffffu, acc_s[ks][2], srcA);
            float v11 = __shfl_sync(0xffffffffu, acc_s[ks][3], srcA);
            float v12 = __shfl_sync(0xffffffffu, acc_s[ks][2], srcB);
            float v13 = __shfl_sync(0xffffffffu, acc_s[ks][3], srcB);
            uint32_t ap[4];
            ap[0] = __float_as_uint(to_tf32(par ? v01 : v00));   // P[g][8ks+t]
            ap[1] = __float_as_uint(to_tf32(par ? v11 : v10));   // P[g+8][8ks+t]
            ap[2] = __float_as_uint(to_tf32(par ? v03 : v02));   // P[g][8ks+t+4]
            ap[3] = __float_as_uint(to_tf32(par ? v13 : v12));   // P[g+8][8ks+t+4]
#pragma unroll
            for (int nt = 0; nt < 8; ++nt) {
                uint32_t bv[2];
                bv[0] = __float_as_uint(Vs[(ks * 8 + t)     * 72 + nt * 8 + g]);
                bv[1] = __float_as_uint(Vs[(ks * 8 + t + 4) * 72 + nt * 8 + g]);
                mma_tf32(acc_o[nt], ap, bv);
            }
        }
    }

    // ---- finalize + store (concat layout, tf32-rounded for next GEMM) ----
    float inv0 = 1.0f / l0r, inv1 = 1.0f / l1r;
    int r0 = q0 + mrow + g, r1 = r0 + 8;
#pragma unroll
    for (int nt = 0; nt < 8; ++nt) {
        int col = h * DHH + nt * 8 + 2 * t;
        float2 o0, o1;
        o0.x = to_tf32(acc_o[nt][0] * inv0); o0.y = to_tf32(acc_o[nt][1] * inv0);
        o1.x = to_tf32(acc_o[nt][2] * inv1); o1.y = to_tf32(acc_o[nt][3] * inv1);
        *(float2*)(attn + ((size_t)(b * SS + r0)) * DD + col) = o0;
        *(float2*)(attn + ((size_t)(b * SS + r1)) * DD + col) = o1;
    }
}

// ---------------- launch ---------------------------------------------------
extern "C" void kernel_launch(void* const* d_in, const int* in_sizes, int n_in,
                              void* d_out, int out_size) {
    const float* x   = (const float*)d_in[0];
    const float* wq  = (const float*)d_in[2];
    const float* wk  = (const float*)d_in[3];
    const float* wv  = (const float*)d_in[4];
    const float* wo  = (const float*)d_in[5];
    const float* w1  = (const float*)d_in[6];
    const float* b1  = (const float*)d_in[7];
    const float* w2  = (const float*)d_in[8];
    const float* b2  = (const float*)d_in[9];
    const float* g1  = (const float*)d_in[10];
    const float* be1 = (const float*)d_in[11];
    const float* g2  = (const float*)d_in[12];
    const float* be2 = (const float*)d_in[13];
    float* out = (float*)d_out;

    float *h, *h2, *wqkv, *wot, *w1t, *w2t, *qkv, *attn, *ff1;
    cudaGetSymbolAddress((void**)&h,    g_h);
    cudaGetSymbolAddress((void**)&h2,   g_h2);
    cudaGetSymbolAddress((void**)&wqkv, g_wqkv);
    cudaGetSymbolAddress((void**)&wot,  g_wot);
    cudaGetSymbolAddress((void**)&w1t,  g_w1t);
    cudaGetSymbolAddress((void**)&w2t,  g_w2t);
    cudaGetSymbolAddress((void**)&qkv,  g_qkv);
    cudaGetSymbolAddress((void**)&attn, g_attn);
    cudaGetSymbolAddress((void**)&ff1,  g_ff1);

    cudaFuncSetAttribute(gemm_tc_kernel<0>, cudaFuncAttributeMaxDynamicSharedMemorySize, GEMM_SMEM);
    cudaFuncSetAttribute(gemm_tc_kernel<1>, cudaFuncAttributeMaxDynamicSharedMemorySize, GEMM_SMEM);
    cudaFuncSetAttribute(gemm_tc_kernel<2>, cudaFuncAttributeMaxDynamicSharedMemorySize, GEMM_SMEM);
    cudaFuncSetAttribute(gemm_tc_kernel<3>, cudaFuncAttributeMaxDynamicSharedMemorySize, GEMM_SMEM);
    cudaFuncSetAttribute(flash_attn_mma_kernel, cudaFuncAttributeMaxDynamicSharedMemorySize, FA_SMEM);

    // weight repacks (per-launch; ~35us total)
    repack_wqkv<<<(3 * DD * DD) / 256, 256>>>(wq, wk, wv, wqkv);
    transpose_kernel<<<dim3(DD / 32, DD / 32),  dim3(32, 8)>>>(wo, wot, DD, DD);
    transpose_kernel<<<dim3(FFD / 32, DD / 32), dim3(32, 8)>>>(w1, w1t, DD, FFD);
    transpose_kernel<<<dim3(DD / 32, FFD / 32), dim3(32, 8)>>>(w2, w2t, FFD, DD);

    // 1. LN1 (tf32-rounded output)
    ln_kernel<<<NROWS, 256>>>(x, g1, be1, h);
    // 2. QKV projection: [8192,1024] @ [1024,3072]
    gemm_tc_kernel<0><<<dim3(3 * DD / 128, NROWS / 128), 256, GEMM_SMEM>>>(
        h, wqkv, qkv, nullptr, nullptr, NROWS, 3 * DD, DD);
    // 3. flash attention (tensor cores)
    flash_attn_mma_kernel<<<dim3(SS / 128, BB * HH), 256, FA_SMEM>>>(qkv, attn);
    // 4. out = x + attn @ wo
    gemm_tc_kernel<1><<<dim3(DD / 128, NROWS / 128), 256, GEMM_SMEM>>>(
        attn, wot, out, nullptr, x, NROWS, DD, DD);
    // 5. LN2
    ln_kernel<<<NROWS, 256>>>(out, g2, be2, h2);
    // 6. ff1 = gelu(h2 @ w1 + b1)  (tf32-rounded)
    gemm_tc_kernel<2><<<dim3(FFD / 128, NROWS / 128), 256, GEMM_SMEM>>>(
        h2, w1t, ff1, b1, nullptr, NROWS, FFD, DD);
    // 7. out = out + ff1 @ w2 + b2
    gemm_tc_kernel<3><<<dim3(DD / 128, NROWS / 128), 256, GEMM_SMEM>>>(
        ff1, w2t, out, b2, out, NROWS, DD, FFD);
}

// round 7
// speedup vs baseline: 3.7093x; 1.0615x over previous
#include <cuda_runtime.h>
#include <math.h>
#include <stdint.h>

// Problem constants
#define BB 4
#define SS 2048
#define DD 1024
#define HH 16
#define DHH 64
#define FFD 4096
#define NROWS (BB*SS)          // 8192

// ---------------- scratch (device globals: allocation-guard safe) ----------
__device__ float g_h   [(size_t)NROWS * DD];        // LN1 out (tf32-rounded)
__device__ float g_h2  [(size_t)NROWS * DD];        // LN2 out (tf32-rounded)
__device__ float g_wqkv[(size_t)3 * DD * DD];       // packed [3072 (N), 1024 (K)]
__device__ float g_wot [(size_t)DD * DD];           // wo^T   [1024, 1024]
__device__ float g_w1t [(size_t)FFD * DD];          // w1^T   [4096, 1024]
__device__ float g_w2t [(size_t)DD * FFD];          // w2^T   [1024, 4096]
__device__ float g_qkv [(size_t)NROWS * 3 * DD];    // [8192, 3072] fp32
__device__ float g_attn[(size_t)NROWS * DD];        // attention out (tf32-rounded)
__device__ float g_ff1 [(size_t)NROWS * FFD];       // FFN hidden (tf32-rounded)

// ---------------- helpers ---------------------------------------------------
__device__ __forceinline__ float to_tf32(float x) {
    uint32_t u;
    asm("cvt.rna.tf32.f32 %0, %1;" : "=r"(u) : "f"(x));
    return __uint_as_float(u);
}

__device__ __forceinline__ uint32_t smem_u32(const void* p) {
    return (uint32_t)__cvta_generic_to_shared(p);
}

__device__ __forceinline__ void cp16(uint32_t dst, const void* src) {
    asm volatile("cp.async.cg.shared.global [%0], [%1], 16;" :: "r"(dst), "l"(src));
}
#define CP_COMMIT() asm volatile("cp.async.commit_group;" ::: "memory")
#define CP_WAIT1()  asm volatile("cp.async.wait_group 1;" ::: "memory")

__device__ __forceinline__ void mma_tf32(float* c, const uint32_t* a, const uint32_t* b) {
    asm volatile(
        "mma.sync.aligned.m16n8k8.row.col.f32.tf32.tf32.f32 "
        "{%0,%1,%2,%3}, {%4,%5,%6,%7}, {%8,%9}, {%0,%1,%2,%3};"
        : "+f"(c[0]), "+f"(c[1]), "+f"(c[2]), "+f"(c[3])
        : "r"(a[0]), "r"(a[1]), "r"(a[2]), "r"(a[3]), "r"(b[0]), "r"(b[1]));
}

__device__ __forceinline__ float gelu_exact(float v) {
    return 0.5f * v * (1.0f + erff(v * 0.70710678118654752f));
}

// ---------------- LayerNorm: one block (256 thr) per row of 1024 ----------
__global__ __launch_bounds__(256) void ln_kernel(const float* __restrict__ x,
                                                 const float* __restrict__ gamma,
                                                 const float* __restrict__ beta,
                                                 float* __restrict__ out) {
    __shared__ float red[8];
    __shared__ float s_mean, s_rstd;
    int row = blockIdx.x, tid = threadIdx.x;
    const float* xr = x + (size_t)row * DD;
    float4 v = *(const float4*)(xr + tid * 4);
    float s = v.x + v.y + v.z + v.w;
#pragma unroll
    for (int off = 16; off; off >>= 1) s += __shfl_xor_sync(0xffffffffu, s, off);
    if ((tid & 31) == 0) red[tid >> 5] = s;
    __syncthreads();
    if (tid == 0) {
        float t = 0.f;
#pragma unroll
        for (int i = 0; i < 8; ++i) t += red[i];
        s_mean = t * (1.0f / DD);
    }
    __syncthreads();
    float mean = s_mean;
    float dx = v.x - mean, dy = v.y - mean, dz = v.z - mean, dw = v.w - mean;
    float sq = dx*dx + dy*dy + dz*dz + dw*dw;
#pragma unroll
    for (int off = 16; off; off >>= 1) sq += __shfl_xor_sync(0xffffffffu, sq, off);
    if ((tid & 31) == 0) red[tid >> 5] = sq;
    __syncthreads();
    if (tid == 0) {
        float t = 0.f;
#pragma unroll
        for (int i = 0; i < 8; ++i) t += red[i];
        s_rstd = rsqrtf(t * (1.0f / DD) + 1e-5f);
    }
    __syncthreads();
    float rstd = s_rstd;
    float4 g4 = *(const float4*)(gamma + tid * 4);
    float4 b4 = *(const float4*)(beta + tid * 4);
    float4 o;
    o.x = to_tf32(dx * rstd * g4.x + b4.x);
    o.y = to_tf32(dy * rstd * g4.y + b4.y);
    o.z = to_tf32(dz * rstd * g4.z + b4.z);
    o.w = to_tf32(dw * rstd * g4.w + b4.w);
    *(float4*)(out + (size_t)row * DD + tid * 4) = o;
}

// ---------------- pack wq/wk/wv [H,D,DH] -> [3072 (N), 1024 (K)] ----------
__global__ __launch_bounds__(256) void repack_wqkv(const float* __restrict__ wq,
                                                   const float* __restrict__ wk,
                                                   const float* __restrict__ wv,
                                                   float* __restrict__ wt) {
    int idx = blockIdx.x * 256 + threadIdx.x;      // over 3072*1024
    int n = idx >> 10;            // output row (N)
    int d = idx & 1023;           // output col (K)
    int part = n >> 10;           // 0:q 1:k 2:v
    int c = n & 1023;
    int h = c >> 6, e = c & 63;
    const float* w = (part == 0) ? wq : (part == 1) ? wk : wv;
    wt[idx] = to_tf32(w[((size_t)h * DD + d) * DHH + e]);
}

// ---------------- transpose [R,C] -> [C,R] with tf32 rounding -------------
__global__ __launch_bounds__(256) void transpose_kernel(const float* __restrict__ in,
                                                        float* __restrict__ out,
                                                        int R, int C) {
    __shared__ float t[32][33];
    int rb = blockIdx.y * 32, cb = blockIdx.x * 32;
#pragma unroll
    for (int i = 0; i < 32; i += 8)
        t[threadIdx.y + i][threadIdx.x] = in[(size_t)(rb + threadIdx.y + i) * C + cb + threadIdx.x];
    __syncthreads();
#pragma unroll
    for (int i = 0; i < 32; i += 8)
        out[(size_t)(cb + threadIdx.y + i) * R + rb + threadIdx.x] =
            to_tf32(t[threadIdx.x][threadIdx.y + i]);
}

// ---------------- tf32 mma.sync GEMM: C[M,N] = A[M,K] @ Wt[N,K]^T ---------
// EPI 0: none   1: +res   2: +bias, gelu, tf32-round   3: +bias +res
// CTA tile 128x128, BK=32 (4 ks-steps per sync epoch), 8 warps (2x4),
// warp tile 64x32 (4x4 m16n8k8). Pad 36 -> conflict-free fragment LDS.
#define BK 32
#define APAD 36
#define HALF_FLOATS (128 * APAD)                  // 4608
#define STAGE_FLOATS (2 * HALF_FLOATS)            // 9216
#define NSTG 3
#define GEMM_SMEM (NSTG * STAGE_FLOATS * 4)       // 110592 bytes

template<int EPI>
__global__ __launch_bounds__(256)
void gemm_tc_kernel(const float* __restrict__ A, const float* __restrict__ Wt,
                    float* __restrict__ C,
                    const float* __restrict__ bias, const float* __restrict__ res,
                    int M, int N, int K) {
    extern __shared__ float smem[];
    uint32_t sbase = smem_u32(smem);
    int tid = threadIdx.x;
    int wid = tid >> 5, lane = tid & 31;
    int g = lane >> 2, t = lane & 3;
    int warp_m = wid >> 2, warp_n = wid & 3;
    int m0 = blockIdx.y << 7, n0 = blockIdx.x << 7;

    const float* Ab = A + (size_t)m0 * K;
    const float* Bb = Wt + (size_t)n0 * K;
    int kt = K >> 5;                               // BK=32 tiles

    float acc[4][4][4] = {};

    // one k-tile = 128 rows x 32 floats per matrix = 8 chunks of 16B per row
    auto load_stage = [&](int s, int jt) {
        uint32_t sA = sbase + s * STAGE_FLOATS * 4;
        uint32_t sB = sA + HALF_FLOATS * 4;
        int k0 = jt << 5;
#pragma unroll
        for (int i = 0; i < 4; ++i) {
            int f = i * 256 + tid;                 // 0..1023
            int row = f >> 3, ch = f & 7;
            uint32_t doff = (uint32_t)(row * (APAD * 4) + ch * 16);
            cp16(sA + doff, Ab + (size_t)row * K + k0 + ch * 4);
            cp16(sB + doff, Bb + (size_t)row * K + k0 + ch * 4);
        }
    };

#pragma unroll
    for (int s = 0; s < NSTG - 1; ++s) { load_stage(s, s); CP_COMMIT(); }

    for (int j = 0; j < kt; ++j) {
        CP_WAIT1();
        __syncthreads();
        const float* As = smem + (j % NSTG) * STAGE_FLOATS;
        const float* Bs = As + HALF_FLOATS;
#pragma unroll
        for (int ks = 0; ks < 4; ++ks) {
            int kb = ks * 8;
            uint32_t a[4][4], b[4][2];
#pragma unroll
            for (int mt = 0; mt < 4; ++mt) {
                int mrow = warp_m * 64 + mt * 16;
                a[mt][0] = __float_as_uint(As[(mrow + g)     * APAD + kb + t]);
                a[mt][1] = __float_as_uint(As[(mrow + g + 8) * APAD + kb + t]);
                a[mt][2] = __float_as_uint(As[(mrow + g)     * APAD + kb + t + 4]);
                a[mt][3] = __float_as_uint(As[(mrow + g + 8) * APAD + kb + t + 4]);
            }
#pragma unroll
            for (int nt = 0; nt < 4; ++nt) {
                int nrow = warp_n * 32 + nt * 8;
                b[nt][0] = __float_as_uint(Bs[(nrow + g) * APAD + kb + t]);
                b[nt][1] = __float_as_uint(Bs[(nrow + g) * APAD + kb + t + 4]);
            }
#pragma unroll
            for (int mt = 0; mt < 4; ++mt)
#pragma unroll
                for (int nt = 0; nt < 4; ++nt)
                    mma_tf32(acc[mt][nt], a[mt], b[nt]);
        }
        if (j + NSTG - 1 < kt) load_stage((j + NSTG - 1) % NSTG, j + NSTG - 1);
        CP_COMMIT();
    }

#pragma unroll
    for (int mt = 0; mt < 4; ++mt) {
#pragma unroll
        for (int nt = 0; nt < 4; ++nt) {
#pragma unroll
            for (int half = 0; half < 2; ++half) {
                int row = m0 + warp_m * 64 + mt * 16 + g + half * 8;
                int col = n0 + warp_n * 32 + nt * 8 + 2 * t;
                float v0 = acc[mt][nt][half * 2 + 0];
                float v1 = acc[mt][nt][half * 2 + 1];
                size_t ga = (size_t)row * N + col;
                if (EPI == 1) {
                    float2 r = *(const float2*)(res + ga);
                    v0 += r.x; v1 += r.y;
                } else if (EPI == 2) {
                    v0 = to_tf32(gelu_exact(v0 + bias[col]));
                    v1 = to_tf32(gelu_exact(v1 + bias[col + 1]));
                } else if (EPI == 3) {
                    float2 r = *(const float2*)(res + ga);
                    v0 += bias[col] + r.x; v1 += bias[col + 1] + r.y;
                }
                float2 o; o.x = v0; o.y = v1;
                *(float2*)(C + ga) = o;
            }
        }
    }
}

// ---------------- Flash attention (causal) with tf32 mma.sync -------------
#define QS_OFF 0
#define KS_OFF (128 * 68)                     // 8704
#define VS_OFF (KS_OFF + 64 * 68)             // 13056
#define FA_SMEM ((VS_OFF + 64 * 72) * 4)      // 70656 bytes

__global__ __launch_bounds__(256) void flash_attn_mma_kernel(const float* __restrict__ qkv,
                                                             float* __restrict__ attn) {
    extern __shared__ float sm[];
    float* Qs = sm + QS_OFF;
    float* Ks = sm + KS_OFF;
    float* Vs = sm + VS_OFF;
    int tid = threadIdx.x;
    int wid = tid >> 5, lane = tid & 31;
    int g = lane >> 2, t = lane & 3;
    int qt = blockIdx.x;
    int b = blockIdx.y >> 4, h = blockIdx.y & 15;
    int q0 = qt * 128;
    const float* qbase = qkv + ((size_t)(b * SS + q0)) * (3 * DD) + h * DHH;
    const float* kbase = qkv + ((size_t)(b * SS)) * (3 * DD) + DD + h * DHH;
    const float* vbase = qkv + ((size_t)(b * SS)) * (3 * DD) + 2 * DD + h * DHH;

#pragma unroll
    for (int it = 0; it < 8; ++it) {
        int f = it * 256 + tid, r = f >> 4, e = (f & 15) << 2;
        float4 v = *(const float4*)(qbase + (size_t)r * (3 * DD) + e);
        float4 w;
        w.x = to_tf32(v.x * 0.125f); w.y = to_tf32(v.y * 0.125f);
        w.z = to_tf32(v.z * 0.125f); w.w = to_tf32(v.w * 0.125f);
        *(float4*)(&Qs[r * 68 + e]) = w;
    }

    float acc_o[8][4] = {};
    float m0r = -INFINITY, m1r = -INFINITY, l0r = 0.f, l1r = 0.f;
    int mrow = wid * 16;
    int ntiles = 2 * qt + 2;

    for (int kt = 0; kt < ntiles; ++kt) {
        __syncthreads();
#pragma unroll
        for (int it = 0; it < 4; ++it) {
            int f = it * 256 + tid, r = f >> 4, e = (f & 15) << 2;
            const float* kp = kbase + (size_t)(kt * 64 + r) * (3 * DD) + e;
            const float* vp = vbase + (size_t)(kt * 64 + r) * (3 * DD) + e;
            float4 kv = *(const float4*)kp;
            float4 vv = *(const float4*)vp;
            float4 kw, vw;
            kw.x = to_tf32(kv.x); kw.y = to_tf32(kv.y); kw.z = to_tf32(kv.z); kw.w = to_tf32(kv.w);
            vw.x = to_tf32(vv.x); vw.y = to_tf32(vv.y); vw.z = to_tf32(vv.z); vw.w = to_tf32(vv.w);
            *(float4*)(&Ks[r * 68 + e]) = kw;
            *(float4*)(&Vs[r * 72 + e]) = vw;
        }
        __syncthreads();

        float acc_s[8][4] = {};
#pragma unroll
        for (int ks = 0; ks < 8; ++ks) {
            int kb = ks * 8;
            uint32_t aq[4];
            aq[0] = __float_as_uint(Qs[(mrow + g)     * 68 + kb + t]);
            aq[1] = __float_as_uint(Qs[(mrow + g + 8) * 68 + kb + t]);
            aq[2] = __float_as_uint(Qs[(mrow + g)     * 68 + kb + t + 4]);
            aq[3] = __float_as_uint(Qs[(mrow + g + 8) * 68 + kb + t + 4]);
#pragma unroll
            for (int nt = 0; nt < 8; ++nt) {
                uint32_t bk[2];
                bk[0] = __float_as_uint(Ks[(nt * 8 + g) * 68 + kb + t]);
                bk[1] = __float_as_uint(Ks[(nt * 8 + g) * 68 + kb + t + 4]);
                mma_tf32(acc_s[nt], aq, bk);
            }
        }

        if (kt >= 2 * qt) {
            int r0 = q0 + mrow + g, r1 = r0 + 8;
#pragma unroll
            for (int nt = 0; nt < 8; ++nt) {
                int c0 = kt * 64 + nt * 8 + 2 * t;
                if (c0     > r0) acc_s[nt][0] = -INFINITY;
                if (c0 + 1 > r0) acc_s[nt][1] = -INFINITY;
                if (c0     > r1) acc_s[nt][2] = -INFINITY;
                if (c0 + 1 > r1) acc_s[nt][3] = -INFINITY;
            }
        }

        float mx0 = -INFINITY, mx1 = -INFINITY;
#pragma unroll
        for (int nt = 0; nt < 8; ++nt) {
            mx0 = fmaxf(mx0, fmaxf(acc_s[nt][0], acc_s[nt][1]));
            mx1 = fmaxf(mx1, fmaxf(acc_s[nt][2], acc_s[nt][3]));
        }
        mx0 = fmaxf(mx0, __shfl_xor_sync(0xffffffffu, mx0, 1));
        mx0 = fmaxf(mx0, __shfl_xor_sync(0xffffffffu, mx0, 2));
        mx1 = fmaxf(mx1, __shfl_xor_sync(0xffffffffu, mx1, 1));
        mx1 = fmaxf(mx1, __shfl_xor_sync(0xffffffffu, mx1, 2));
        float mn0 = fmaxf(m0r, mx0), mn1 = fmaxf(m1r, mx1);
        float al0 = __expf(m0r - mn0), al1 = __expf(m1r - mn1);
        float rs0 = 0.f, rs1 = 0.f;
#pragma unroll
        for (int nt = 0; nt < 8; ++nt) {
            acc_s[nt][0] = __expf(acc_s[nt][0] - mn0);
            acc_s[nt][1] = __expf(acc_s[nt][1] - mn0);
            acc_s[nt][2] = __expf(acc_s[nt][2] - mn1);
            acc_s[nt][3] = __expf(acc_s[nt][3] - mn1);
            rs0 += acc_s[nt][0] + acc_s[nt][1];
            rs1 += acc_s[nt][2] + acc_s[nt][3];
        }
        rs0 += __shfl_xor_sync(0xffffffffu, rs0, 1);
        rs0 += __shfl_xor_sync(0xffffffffu, rs0, 2);
        rs1 += __shfl_xor_sync(0xffffffffu, rs1, 1);
        rs1 += __shfl_xor_sync(0xffffffffu, rs1, 2);
        l0r = l0r * al0 + rs0;  m0r = mn0;
        l1r = l1r * al1 + rs1;  m1r = mn1;
#pragma unroll
        for (int nt = 0; nt < 8; ++nt) {
            acc_o[nt][0] *= al0; acc_o[nt][1] *= al0;
            acc_o[nt][2] *= al1; acc_o[nt][3] *= al1;
        }

        int base = lane & ~3;
        int srcA = base | (t >> 1);
        int srcB = srcA + 2;
        int par = t & 1;
#pragma unroll
        for (int ks = 0; ks < 8; ++ks) {
            float v00 = __shfl_sync(0xffffffffu, acc_s[ks][0], srcA);
            float v01 = __shfl_sync(0xffffffffu, acc_s[ks][1], srcA);
            float v02 = __shfl_sync(0xffffffffu, acc_s[ks][0], srcB);
            float v03 = __shfl_sync(0xffffffffu, acc_s[ks][1], srcB);
            float v10 = __shfl_sync(0xffffffffu, acc_s[ks][2], srcA);
            float v11 = __shfl_sync(0xffffffffu, acc_s[ks][3], srcA);
            float v12 = __shfl_sync(0xffffffffu, acc_s[ks][2], srcB);
            float v13 = __shfl_sync(0xffffffffu, acc_s[ks][3], srcB);
            uint32_t ap[4];
            ap[0] = __float_as_uint(to_tf32(par ? v01 : v00));
            ap[1] = __float_as_uint(to_tf32(par ? v11 : v10));
            ap[2] = __float_as_uint(to_tf32(par ? v03 : v02));
            ap[3] = __float_as_uint(to_tf32(par ? v13 : v12));
#pragma unroll
            for (int nt = 0; nt < 8; ++nt) {
                uint32_t bv[2];
                bv[0] = __float_as_uint(Vs[(ks * 8 + t)     * 72 + nt * 8 + g]);
                bv[1] = __float_as_uint(Vs[(ks * 8 + t + 4) * 72 + nt * 8 + g]);
                mma_tf32(acc_o[nt], ap, bv);
            }
        }
    }

    float inv0 = 1.0f / l0r, inv1 = 1.0f / l1r;
    int r0 = q0 + mrow + g, r1 = r0 + 8;
#pragma unroll
    for (int nt = 0; nt < 8; ++nt) {
        int col = h * DHH + nt * 8 + 2 * t;
        float2 o0, o1;
        o0.x = to_tf32(acc_o[nt][0] * inv0); o0.y = to_tf32(acc_o[nt][1] * inv0);
        o1.x = to_tf32(acc_o[nt][2] * inv1); o1.y = to_tf32(acc_o[nt][3] * inv1);
        *(float2*)(attn + ((size_t)(b * SS + r0)) * DD + col) = o0;
        *(float2*)(attn + ((size_t)(b * SS + r1)) * DD + col) = o1;
    }
}

// ---------------- launch ---------------------------------------------------
extern "C" void kernel_launch(void* const* d_in, const int* in_sizes, int n_in,
                              void* d_out, int out_size) {
    const float* x   = (const float*)d_in[0];
    const float* wq  = (const float*)d_in[2];
    const float* wk  = (const float*)d_in[3];
    const float* wv  = (const float*)d_in[4];
    const float* wo  = (const float*)d_in[5];
    const float* w1  = (const float*)d_in[6];
    const float* b1  = (const float*)d_in[7];
    const float* w2  = (const float*)d_in[8];
    const float* b2  = (const float*)d_in[9];
    const float* g1  = (const float*)d_in[10];
    const float* be1 = (const float*)d_in[11];
    const float* g2  = (const float*)d_in[12];
    const float* be2 = (const float*)d_in[13];
    float* out = (float*)d_out;

    float *h, *h2, *wqkv, *wot, *w1t, *w2t, *qkv, *attn, *ff1;
    cudaGetSymbolAddress((void**)&h,    g_h);
    cudaGetSymbolAddress((void**)&h2,   g_h2);
    cudaGetSymbolAddress((void**)&wqkv, g_wqkv);
    cudaGetSymbolAddress((void**)&wot,  g_wot);
    cudaGetSymbolAddress((void**)&w1t,  g_w1t);
    cudaGetSymbolAddress((void**)&w2t,  g_w2t);
    cudaGetSymbolAddress((void**)&qkv,  g_qkv);
    cudaGetSymbolAddress((void**)&attn, g_attn);
    cudaGetSymbolAddress((void**)&ff1,  g_ff1);

    cudaFuncSetAttribute(gemm_tc_kernel<0>, cudaFuncAttributeMaxDynamicSharedMemorySize, GEMM_SMEM);
    cudaFuncSetAttribute(gemm_tc_kernel<1>, cudaFuncAttributeMaxDynamicSharedMemorySize, GEMM_SMEM);
    cudaFuncSetAttribute(gemm_tc_kernel<2>, cudaFuncAttributeMaxDynamicSharedMemorySize, GEMM_SMEM);
    cudaFuncSetAttribute(gemm_tc_kernel<3>, cudaFuncAttributeMaxDynamicSharedMemorySize, GEMM_SMEM);
    cudaFuncSetAttribute(flash_attn_mma_kernel, cudaFuncAttributeMaxDynamicSharedMemorySize, FA_SMEM);

    // weight repacks (per-launch; ~45us total)
    repack_wqkv<<<(3 * DD * DD) / 256, 256>>>(wq, wk, wv, wqkv);
    transpose_kernel<<<dim3(DD / 32, DD / 32),  dim3(32, 8)>>>(wo, wot, DD, DD);
    transpose_kernel<<<dim3(FFD / 32, DD / 32), dim3(32, 8)>>>(w1, w1t, DD, FFD);
    transpose_kernel<<<dim3(DD / 32, FFD / 32), dim3(32, 8)>>>(w2, w2t, FFD, DD);

    // 1. LN1 (tf32-rounded output)
    ln_kernel<<<NROWS, 256>>>(x, g1, be1, h);
    // 2. QKV projection: [8192,1024] @ [1024,3072]
    gemm_tc_kernel<0><<<dim3(3 * DD / 128, NROWS / 128), 256, GEMM_SMEM>>>(
        h, wqkv, qkv, nullptr, nullptr, NROWS, 3 * DD, DD);
    // 3. flash attention (tensor cores)
    flash_attn_mma_kernel<<<dim3(SS / 128, BB * HH), 256, FA_SMEM>>>(qkv, attn);
    // 4. out = x + attn @ wo
    gemm_tc_kernel<1><<<dim3(DD / 128, NROWS / 128), 256, GEMM_SMEM>>>(
        attn, wot, out, nullptr, x, NROWS, DD, DD);
    // 5. LN2
    ln_kernel<<<NROWS, 256>>>(out, g2, be2, h2);
    // 6. ff1 = gelu(h2 @ w1 + b1)  (tf32-rounded)
    gemm_tc_kernel<2><<<dim3(FFD / 128, NROWS / 128), 256, GEMM_SMEM>>>(
        h2, w1t, ff1, b1, nullptr, NROWS, FFD, DD);
    // 7. out = out + ff1 @ w2 + b2
    gemm_tc_kernel<3><<<dim3(DD / 128, NROWS / 128), 256, GEMM_SMEM>>>(
        ff1, w2t, out, b2, out, NROWS, DD, FFD);
}